// round 17
// baseline (speedup 1.0000x reference)
#include <cuda_runtime.h>
#include <math.h>

#define H 1024
#define L 4096
#define V 29
#define NB 128           // blocks (<= SM count, 1 block/SM -> co-resident)
#define NT 1024          // threads per block
#define WPB 32           // warps per block

// ---------------- scratch (device globals) ----------------------------------
__device__ float g_scores[L];
__device__ float g_hh[4 * H];          // W_hh @ h0 partial gates
__device__ float g_attn_applied[H];
__device__ float g_x[H];
__device__ float g_gates[4 * H];
__device__ unsigned g_cnt = 0;
__device__ volatile unsigned g_flag = 0;

// ---------------- helpers ----------------------------------------------------
__device__ __forceinline__ float warp_sum(float v) {
#pragma unroll
    for (int o = 16; o; o >>= 1) v += __shfl_xor_sync(0xffffffffu, v, o);
    return v;
}
__device__ __forceinline__ float warp_max(float v) {
#pragma unroll
    for (int o = 16; o; o >>= 1) v = fmaxf(v, __shfl_xor_sync(0xffffffffu, v, o));
    return v;
}
__device__ __forceinline__ float sigmoidf_(float x) { return 1.0f / (1.0f + expf(-x)); }

// sense-reversing grid barrier. Requires all NB blocks co-resident.
// Counter self-resets; flag must return to 0 at kernel end (use EVEN # of barriers).
__device__ __forceinline__ void grid_barrier(unsigned sense) {
    __syncthreads();
    if (threadIdx.x == 0) {
        __threadfence();
        unsigned old = atomicAdd(&g_cnt, 1u);
        if (old == NB - 1) {
            g_cnt = 0;
            __threadfence();
            g_flag = sense;
        } else {
            while (g_flag != sense) { __nanosleep(64); }
        }
        __threadfence();
    }
    __syncthreads();
}

__device__ __forceinline__ float dot4(float4 a, float4 b) {
    return a.x * b.x + a.y * b.y + a.z * b.z + a.w * b.w;
}

// ---------------- the whole decoder step in one kernel -----------------------
__global__ void __launch_bounds__(NT, 1)
k_decoder(const int* __restrict__ tok,
          const float* __restrict__ h0,
          const float* __restrict__ c0,
          const float* __restrict__ enc,
          const float* __restrict__ emb,
          const float* __restrict__ attn_W,
          const float* __restrict__ attn_b,
          const float* __restrict__ comb_W,
          const float* __restrict__ comb_b,
          const float* __restrict__ W_ih,
          const float* __restrict__ W_hh,
          const float* __restrict__ b_ih,
          const float* __restrict__ b_hh,
          const float* __restrict__ out_W,
          const float* __restrict__ out_b,
          float* __restrict__ out) {
    __shared__ float s[2 * H];
    __shared__ float red[32];
    __shared__ float bcast;
    __shared__ float wts[32];
    __shared__ float z[32];

    const int t = threadIdx.x;          // 0..1023
    const int warp = t >> 5, lane = t & 31;
    float* attn_out = out + V + 2 * H;  // d_out layout: [lp | h | c | attn_w]

    // ============ Phase A: attn scores + W_hh@h0 (independent, fused) =======
    {
        const float* erow = emb + (size_t)tok[0] * H;
        s[t] = erow[t];
        s[H + t] = h0[t];
        if (blockIdx.x == 0) g_attn_applied[t] = 0.0f;
        __syncthreads();

        int gw = blockIdx.x * WPB + warp;   // 0..4095

        // scores row gw: dot over 2H
        {
            const float4* w = (const float4*)(attn_W + (size_t)gw * (2 * H));
            const float4* c = (const float4*)s;
            float acc = 0.0f;
#pragma unroll 4
            for (int j = lane; j < (2 * H) / 4; j += 32) acc += dot4(w[j], c[j]);
            acc = warp_sum(acc);
            if (lane == 0) g_scores[gw] = acc + attn_b[gw];
        }
        // hh row gw: dot over H
        {
            const float4* w = (const float4*)(W_hh + (size_t)gw * H);
            const float4* c = (const float4*)(s + H);
            float acc = 0.0f;
#pragma unroll 4
            for (int j = lane; j < H / 4; j += 32) acc += dot4(w[j], c[j]);
            acc = warp_sum(acc);
            if (lane == 0) g_hh[gw] = acc;
        }
    }
    grid_barrier(1);

    // ============ Phase B: softmax (redundant per-block) + weighted enc sum ==
    {
        float sc[4];
        float m = -1e30f;
#pragma unroll
        for (int k = 0; k < 4; k++) {
            sc[k] = g_scores[t + k * 1024];
            m = fmaxf(m, sc[k]);
        }
        m = warp_max(m);
        if (lane == 0) red[warp] = m;
        __syncthreads();
        if (warp == 0) {
            float x = red[lane];
            x = warp_max(x);
            if (lane == 0) bcast = x;
        }
        __syncthreads();
        const float M = bcast;

        float sum = 0.0f;
#pragma unroll
        for (int k = 0; k < 4; k++) sum += expf(sc[k] - M);
        sum = warp_sum(sum);
        __syncthreads();
        if (lane == 0) red[warp] = sum;
        __syncthreads();
        if (warp == 0) {
            float x = red[lane];
            x = warp_sum(x);
            if (lane == 0) bcast = x;
        }
        __syncthreads();
        const float invS = 1.0f / bcast;

        const int lb = blockIdx.x * 32;    // this block's 32 encoder rows
        if (t < 32) {
            float w = expf(g_scores[lb + t] - M) * invS;
            wts[t] = w;
            attn_out[lb + t] = w;
        }
        __syncthreads();

        // thread t owns column t (1024 threads = H columns), fully coalesced
        float acc = 0.0f;
        const float* e = enc + (size_t)lb * H + t;
#pragma unroll 8
        for (int r = 0; r < 32; r++) acc += wts[r] * e[(size_t)r * H];
        atomicAdd(&g_attn_applied[t], acc);
    }
    grid_barrier(0);

    // ============ Phase C: x = relu(comb_W @ [emb; attn_applied] + b) =======
    {
        s[H + t] = g_attn_applied[t];      // emb still resident in s[0..H)
        __syncthreads();

        int row = blockIdx.x * 8 + (warp >> 2);   // 8 rows/block, 4 warps/row
        int part = warp & 3;
        const float4* w = (const float4*)(comb_W + (size_t)row * (2 * H));
        const float4* c = (const float4*)s;
        float acc = 0.0f;
        int j0 = part * 128 + lane;
#pragma unroll
        for (int j = j0; j < part * 128 + 128; j += 32) acc += dot4(w[j], c[j]);
        acc = warp_sum(acc);
        if (lane == 0) red[warp] = acc;
        __syncthreads();
        if (warp == 0 && lane < 8) {
            int r2 = blockIdx.x * 8 + lane;
            float v = red[lane * 4] + red[lane * 4 + 1] +
                      red[lane * 4 + 2] + red[lane * 4 + 3];
            g_x[r2] = fmaxf(v + comb_b[r2], 0.0f);
        }
    }
    grid_barrier(1);

    // ============ Phase D: gates = W_ih@x + hh + b_ih + b_hh ================
    {
        s[t] = g_x[t];
        s[H + t] = h0[t];
        __syncthreads();

        int row = blockIdx.x * 32 + warp;  // 4096 rows over 128 blocks
        const float4* w = (const float4*)(W_ih + (size_t)row * H);
        const float4* c = (const float4*)s;
        float acc = 0.0f;
#pragma unroll 4
        for (int j = lane; j < H / 4; j += 32) acc += dot4(w[j], c[j]);
        acc = warp_sum(acc);
        if (lane == 0)
            g_gates[row] = acc + g_hh[row] + b_ih[row] + b_hh[row];
    }
    grid_barrier(0);

    // ============ Phase E: LSTM pointwise + out proj + log_softmax =========
    if (blockIdx.x == 0) {
        float ig = g_gates[t];
        float fg = g_gates[H + t];
        float gg = g_gates[2 * H + t];
        float og = g_gates[3 * H + t];
        float c = sigmoidf_(fg) * c0[t] + sigmoidf_(ig) * tanhf(gg);
        float h = sigmoidf_(og) * tanhf(c);
        out[V + t] = h;
        out[V + H + t] = c;
        s[t] = h;
        __syncthreads();

        if (warp < V) {
            const float4* wr = (const float4*)(out_W + (size_t)warp * H);
            const float4* hv = (const float4*)s;
            float acc = 0.0f;
#pragma unroll
            for (int k = lane; k < H / 4; k += 32) acc += dot4(wr[k], hv[k]);
            acc = warp_sum(acc);
            if (lane == 0) z[warp] = acc + out_b[warp];
        }
        __syncthreads();

        // warp-parallel log_softmax over V=29 (replaces serial t==0 loop)
        if (warp == 0) {
            float v = (lane < V) ? z[lane] : -1e30f;
            float m = warp_max(v);
            float e = (lane < V) ? expf(v - m) : 0.0f;
            float ssum = warp_sum(e);
            float ls = m + logf(ssum);
            if (lane < V) out[lane] = v - ls;
        }
    }
}

// ---------------- launch ------------------------------------------------------
extern "C" void kernel_launch(void* const* d_in, const int* in_sizes, int n_in,
                              void* d_out, int out_size) {
    const int*   tok    = (const int*)  d_in[0];
    const float* h0     = (const float*)d_in[1];
    const float* c0     = (const float*)d_in[2];
    const float* enc    = (const float*)d_in[3];
    const float* emb    = (const float*)d_in[4];
    const float* attn_W = (const float*)d_in[5];
    const float* attn_b = (const float*)d_in[6];
    const float* comb_W = (const float*)d_in[7];
    const float* comb_b = (const float*)d_in[8];
    const float* W_ih   = (const float*)d_in[9];
    const float* W_hh   = (const float*)d_in[10];
    const float* b_ih   = (const float*)d_in[11];
    const float* b_hh   = (const float*)d_in[12];
    const float* out_W  = (const float*)d_in[13];
    const float* out_b  = (const float*)d_in[14];
    float* out = (float*)d_out;

    k_decoder<<<NB, NT>>>(tok, h0, c0, enc, emb, attn_W, attn_b,
                          comb_W, comb_b, W_ih, W_hh, b_ih, b_hh,
                          out_W, out_b, out);
}